// round 1
// baseline (speedup 1.0000x reference)
#include <cuda_runtime.h>

// PartialSum: out[b, p] = sum over 64 contiguous floats of x[b, p*64 : (p+1)*64]
// x: [2048, 65536] f32  -> out: [2048, 1024] f32
// Strategy: 1 float4 per thread (coalesced LDG.128), 16 threads per partition,
// shfl_down tree-reduce within the 16-lane group, group leader writes output.

__global__ void __launch_bounds__(256) partial_sum_kernel(
    const float4* __restrict__ x4, float* __restrict__ out)
{
    int tid = blockIdx.x * blockDim.x + threadIdx.x;   // one float4 per thread
    float4 v = __ldg(&x4[tid]);
    float s = (v.x + v.y) + (v.z + v.w);

    // Reduce across the 16-lane group that owns one 64-element partition.
    #pragma unroll
    for (int off = 8; off > 0; off >>= 1)
        s += __shfl_down_sync(0xffffffffu, s, off, 16);

    if ((threadIdx.x & 15) == 0)
        out[tid >> 4] = s;
}

extern "C" void kernel_launch(void* const* d_in, const int* in_sizes, int n_in,
                              void* d_out, int out_size)
{
    const float4* x4 = (const float4*)d_in[0];
    float* out = (float*)d_out;

    // total elements = in_sizes[0]; float4 count = /4; threads = float4 count
    long long n = (long long)in_sizes[0];
    int n4 = (int)(n / 4);                 // 33,554,432
    int threads = 256;
    int blocks = (n4 + threads - 1) / threads;  // 131,072

    partial_sum_kernel<<<blocks, threads>>>(x4, out);
}